// round 13
// baseline (speedup 1.0000x reference)
#include <cuda_runtime.h>
#include <cuda_fp16.h>
#include <cstdint>
#include <cfloat>

#define N_NODES 100000
#define N_EDGES 500000
#define N_REL 4
#define N_LAYERS 4
#define IN_FEAT 64
#define EMB 128
#define N_GRAPHS 64
#define SCAN_NB 98   // ceil(100000/1024)

// ---------------- scratch (device globals; no allocation allowed) ----------------
__device__ __half g_out16[(size_t)N_NODES * EMB];        // root result fp16
__device__ __half g_tmp[(size_t)N_REL * N_NODES * EMB];  // 4 conv outputs fp16 (102MB, L2-resident)
__device__ __half g_h16[(size_t)N_NODES * EMB];          // h fp16 (GEMM A / pool input)
__device__ __half g_x16[(size_t)N_NODES * IN_FEAT];
// 21 weight matrices, transposed [N=128][K=128] fp16:
// slot 0 = emb (K rows 64..127 zero), 1..4 = root, 5..20 = conv (l*4+r)
__device__ __half g_w16[(size_t)21 * 128 * 128];
__device__ int   g_csr_src[(size_t)N_REL * N_EDGES];
__device__ int   g_deg[(size_t)N_REL * N_NODES];
__device__ int   g_off[(size_t)N_REL * (N_NODES + 1)];
__device__ int   g_cur[(size_t)N_REL * N_NODES];
__device__ int   g_bsum[(size_t)N_REL * 128];

// ---------------- helpers ----------------
__device__ __forceinline__ uint32_t smem_u32(const void* p) {
    uint32_t a;
    asm("{ .reg .u64 t; cvta.to.shared.u64 t, %1; cvt.u32.u64 %0, t; }" : "=r"(a) : "l"(p));
    return a;
}
__device__ __forceinline__ void ldsm4(uint32_t& r0, uint32_t& r1, uint32_t& r2, uint32_t& r3,
                                      uint32_t addr) {
    asm volatile("ldmatrix.sync.aligned.m8n8.x4.shared.b16 {%0,%1,%2,%3}, [%4];"
                 : "=r"(r0), "=r"(r1), "=r"(r2), "=r"(r3) : "r"(addr));
}
__device__ __forceinline__ void mma16816(float* d, const uint32_t* a, const uint32_t* b) {
    asm volatile(
        "mma.sync.aligned.m16n8k16.row.col.f32.f16.f16.f32 "
        "{%0,%1,%2,%3}, {%4,%5,%6,%7}, {%8,%9}, {%0,%1,%2,%3};"
        : "+f"(d[0]), "+f"(d[1]), "+f"(d[2]), "+f"(d[3])
        : "r"(a[0]), "r"(a[1]), "r"(a[2]), "r"(a[3]), "r"(b[0]), "r"(b[1]));
}
#define CP_ASYNC16(dst, src, n) \
    asm volatile("cp.async.ca.shared.global [%0], [%1], 16, %2;" \
                 :: "r"(dst), "l"(src), "r"(n))

// ---------------- utility kernels ----------------
__global__ void zero_int_kernel(int* p, int n) {
    int i = blockIdx.x * blockDim.x + threadIdx.x;
    if (i < n) p[i] = 0;
}
__global__ void zero_float_kernel(float* p, int n) {
    int i = blockIdx.x * blockDim.x + threadIdx.x;
    if (i < n) p[i] = 0.0f;
}

__global__ void hist_all_kernel(const int* __restrict__ e0, const int* __restrict__ e1,
                                const int* __restrict__ e2, const int* __restrict__ e3,
                                int* __restrict__ deg) {
    int r = blockIdx.y;
    const int* dst = ((r == 0) ? e0 : (r == 1) ? e1 : (r == 2) ? e2 : e3) + N_EDGES;
    int i = blockIdx.x * 256 + threadIdx.x;
    if (i < N_EDGES) atomicAdd(&deg[(size_t)r * N_NODES + dst[i]], 1);
}

// -------- 3-phase parallel exclusive scan of deg -> off (all relations) --------
__global__ void scan_p1(const int* __restrict__ deg, int* __restrict__ bsum) {
    int r = blockIdx.y, b = blockIdx.x, t = threadIdx.x;
    const int* d = deg + (size_t)r * N_NODES;
    int base = b * 1024 + t * 4;
    int s = 0;
#pragma unroll
    for (int j = 0; j < 4; j++) {
        int idx = base + j;
        if (idx < N_NODES) s += d[idx];
    }
    __shared__ int sm[256];
    sm[t] = s;
    __syncthreads();
    for (int o = 128; o > 0; o >>= 1) {
        if (t < o) sm[t] += sm[t + o];
        __syncthreads();
    }
    if (t == 0) bsum[r * 128 + b] = sm[0];
}
__global__ void scan_p2(int* __restrict__ bsum) {
    __shared__ int sm[512];
    int t = threadIdx.x;
    int r = t >> 7;
    int i = t & 127;
    int v = (i < SCAN_NB) ? bsum[r * 128 + i] : 0;
    sm[t] = v;
    __syncthreads();
    for (int d = 1; d < 128; d <<= 1) {
        int add = (i >= d) ? sm[t - d] : 0;
        __syncthreads();
        sm[t] += add;
        __syncthreads();
    }
    int excl = (i == 0) ? 0 : sm[t - 1];
    if (i < SCAN_NB) bsum[r * 128 + i] = excl;
}
__global__ void scan_p3(const int* __restrict__ deg, const int* __restrict__ bsum,
                        int* __restrict__ off, int* __restrict__ cur) {
    int r = blockIdx.y, b = blockIdx.x, t = threadIdx.x;
    const int* d = deg + (size_t)r * N_NODES;
    int* o = off + (size_t)r * (N_NODES + 1);
    int* c = cur + (size_t)r * N_NODES;
    int base = b * 1024 + t * 4;
    int v[4], pre[4];
    int s = 0;
#pragma unroll
    for (int j = 0; j < 4; j++) {
        int idx = base + j;
        v[j] = (idx < N_NODES) ? d[idx] : 0;
        pre[j] = s;
        s += v[j];
    }
    __shared__ int sm[256];
    sm[t] = s;
    __syncthreads();
    for (int dd = 1; dd < 256; dd <<= 1) {
        int add = (t >= dd) ? sm[t - dd] : 0;
        __syncthreads();
        sm[t] += add;
        __syncthreads();
    }
    int texcl = (t == 0) ? 0 : sm[t - 1];
    int boff = bsum[r * 128 + b];
#pragma unroll
    for (int j = 0; j < 4; j++) {
        int idx = base + j;
        if (idx < N_NODES) {
            int val = boff + texcl + pre[j];
            o[idx] = val;
            c[idx] = val;
        }
    }
    if (b == SCAN_NB - 1 && t == 255) o[N_NODES] = boff + sm[255];
}

__global__ void fill_all_kernel(const int* __restrict__ e0, const int* __restrict__ e1,
                                const int* __restrict__ e2, const int* __restrict__ e3,
                                int* __restrict__ cur, int* __restrict__ csr) {
    int r = blockIdx.y;
    const int* eptr = (r == 0) ? e0 : (r == 1) ? e1 : (r == 2) ? e2 : e3;
    int i = blockIdx.x * 256 + threadIdx.x;
    if (i < N_EDGES) {
        int dnode = eptr[N_EDGES + i];
        int pos = atomicAdd(&cur[(size_t)r * N_NODES + dnode], 1);
        csr[(size_t)r * N_EDGES + pos] = eptr[i];
    }
}

// ---------------- conversion kernels ----------------
__global__ void conv_x_kernel(const float* __restrict__ x, __half* __restrict__ x16, int n) {
    int i = blockIdx.x * blockDim.x + threadIdx.x;
    if (i < n) x16[i] = __float2half(x[i]);
}
__global__ void conv_w_kernel(const float* __restrict__ emb_w,
                              const float* __restrict__ root_w,
                              const float* __restrict__ conv_w,
                              __half* __restrict__ w16) {
    int idx = blockIdx.x * blockDim.x + threadIdx.x;
    if (idx >= 21 * 128 * 128) return;
    int s = idx >> 14;
    int rem = idx & 16383;
    int n = rem >> 7;
    int k = rem & 127;
    float v;
    if (s == 0)      v = (k < IN_FEAT) ? emb_w[(size_t)k * EMB + n] : 0.0f;
    else if (s <= 4) v = root_w[((size_t)(s - 1) * EMB + k) * EMB + n];
    else             v = conv_w[((size_t)(s - 5) * EMB + k) * EMB + n];
    w16[idx] = __float2half(v);
}

// ---------------- fp16 mma.sync GEMM: C[M,128] = A[M,K] @ W^T (+ bias) ----------------
// Single fp16 pass. B preloaded to smem once (full K); A streamed through a
// 3-stage cp.async pipeline.
// mode==1 (layer batch): y==0 -> root slot (slotArg>>16), out fp16 dst0 + bias;
//   y==1..4 -> conv slot (slotArg&0xFFFF)+y, out fp16 tmp + (y-1)*MN.
// mode==2 (embed): slot = slotArg, out fp16 dst0 + bias.
#define BK 32
#define SSTR 40
#define BSTR 136
#define NSTAGE 3
#define A_TILE_B (128 * SSTR * 2)            // 10240
#define B_TILE_B (128 * BSTR * 2)            // 34816
#define GEMM_SMEM (B_TILE_B + NSTAGE * A_TILE_B)  // 65536

__global__ __launch_bounds__(256, 2) void gemm_mma(
    const __half* __restrict__ A, int M, int K,
    const __half* __restrict__ w_base, int slotArg, int mode,
    const float* __restrict__ bias0,
    __half* __restrict__ dst0,
    __half* __restrict__ tmp)
{
    extern __shared__ __half sm_dyn[];
    uint32_t bs_u = smem_u32(sm_dyn);
    uint32_t as_u = bs_u + B_TILE_B;

    int y = blockIdx.y;
    int slot = (mode == 1) ? ((y == 0) ? (slotArg >> 16) : ((slotArg & 0xFFFF) + y))
                           : slotArg;
    const __half* W = w_base + (size_t)slot * 16384;

    int tid = threadIdx.x;
    int wid = tid >> 5;
    int lane = tid & 31;
    int wm = wid & 1;
    int wn = wid >> 1;
    int r0 = blockIdx.x * 128;

    // ---- preload B (full 128x128) into smem (group 0) ----
    for (int idx = tid; idx < 2048; idx += 256) {
        int row = idx >> 4;
        int ch = idx & 15;
        uint32_t soff = (uint32_t)(row * BSTR + ch * 8) * 2u;
        CP_ASYNC16(bs_u + soff,
                   (uint64_t)__cvta_generic_to_global(W + (size_t)row * 128 + ch * 8), 16);
    }
    asm volatile("cp.async.commit_group;");

    float acc[4][4][4];
#pragma unroll
    for (int i = 0; i < 4; i++)
#pragma unroll
        for (int j = 0; j < 4; j++)
#pragma unroll
            for (int q = 0; q < 4; q++) acc[i][j][q] = 0.0f;

    int l_within = lane & 7;
    int l_sel = lane >> 3;
    int nch = K >> 5;

    int li0 = tid * 2, li1 = tid * 2 + 1;
    int lr0 = li0 >> 2, lc0 = li0 & 3;
    int lr1 = li1 >> 2, lc1 = li1 & 3;

    auto load_stage = [&](int kc, int st) {
        int k0 = kc * BK;
#pragma unroll
        for (int i = 0; i < 2; i++) {
            int row = i ? lr1 : lr0;
            int ch  = i ? lc1 : lc0;
            int gr = r0 + row;
            int ok = (gr < M) ? 16 : 0;
            int grc = (gr < M) ? gr : 0;
            uint32_t soff = (uint32_t)(row * SSTR + ch * 8) * 2u;
            CP_ASYNC16(as_u + (uint32_t)st * A_TILE_B + soff,
                       (uint64_t)__cvta_generic_to_global(A + (size_t)grc * K + k0 + ch * 8), ok);
        }
        asm volatile("cp.async.commit_group;");
    };

    // prefetch 2 stages
    load_stage(0, 0);
    if (nch > 1) load_stage(1, 1);

    for (int kc = 0; kc < nch; kc++) {
        int st = kc % NSTAGE;
        if (kc + 2 < nch) load_stage(kc + 2, (kc + 2) % NSTAGE);
        int pend = nch - 1 - kc;
        if (pend >= 2)      asm volatile("cp.async.wait_group 2;");
        else if (pend == 1) asm volatile("cp.async.wait_group 1;");
        else                asm volatile("cp.async.wait_group 0;");
        __syncthreads();

        uint32_t a_stage = as_u + (uint32_t)st * A_TILE_B;
#pragma unroll
        for (int ks = 0; ks < 2; ks++) {
            uint32_t af[4][4];
            uint32_t bf[4][2];
#pragma unroll
            for (int fm = 0; fm < 4; fm++) {
                int arow = wm * 64 + fm * 16 + (l_sel & 1) * 8 + l_within;
                int acol = ks * 16 + (l_sel >> 1) * 8;
                ldsm4(af[fm][0], af[fm][1], af[fm][2], af[fm][3],
                      a_stage + (uint32_t)(arow * SSTR + acol) * 2u);
            }
#pragma unroll
            for (int g = 0; g < 2; g++) {
                int brow = wn * 32 + g * 16 + (l_sel >> 1) * 8 + l_within;
                int bcol = kc * 32 + ks * 16 + (l_sel & 1) * 8;
                uint32_t r0v, r1v, r2v, r3v;
                ldsm4(r0v, r1v, r2v, r3v,
                      bs_u + (uint32_t)(brow * BSTR + bcol) * 2u);
                bf[2 * g + 0][0] = r0v; bf[2 * g + 0][1] = r1v;
                bf[2 * g + 1][0] = r2v; bf[2 * g + 1][1] = r3v;
            }
#pragma unroll
            for (int fm = 0; fm < 4; fm++)
#pragma unroll
                for (int fn = 0; fn < 4; fn++)
                    mma16816(acc[fm][fn], af[fm], bf[fn]);
        }
        __syncthreads();
    }

    // ---- epilogue (all fp16 outputs) ----
    int qrow = lane >> 2;
    int qcol = (lane & 3) * 2;
    bool add_bias = (mode == 2) || (mode == 1 && y == 0);
    __half* dst = (mode == 1 && y > 0)
                ? (tmp + (size_t)(y - 1) * (size_t)N_NODES * EMB)
                : dst0;
#pragma unroll
    for (int fm = 0; fm < 4; fm++) {
#pragma unroll
        for (int half_i = 0; half_i < 2; half_i++) {
            int grow = r0 + wm * 64 + fm * 16 + qrow + half_i * 8;
            if (grow >= M) continue;
#pragma unroll
            for (int fn = 0; fn < 4; fn++) {
                int col = wn * 32 + fn * 8 + qcol;
                float v0 = acc[fm][fn][half_i * 2 + 0];
                float v1 = acc[fm][fn][half_i * 2 + 1];
                if (add_bias) {
                    v0 += __ldg(&bias0[col]);
                    v1 += __ldg(&bias0[col + 1]);
                }
                *(__half2*)(dst + (size_t)grow * EMB + col) = __floats2half2_rn(v0, v1);
            }
        }
    }
}

// ---------------- fully-fused per-layer aggregation (warp per node, 4-wide) ----------------
__device__ __forceinline__ void fmax4(float4& m, const __half* msg, int src, int lane) {
    uint2 u = *(const uint2*)(msg + (size_t)src * EMB + lane * 4);
    float2 a = __half22float2(*(__half2*)&u.x);
    float2 b = __half22float2(*(__half2*)&u.y);
    m.x = fmaxf(m.x, a.x);
    m.y = fmaxf(m.y, a.y);
    m.z = fmaxf(m.z, b.x);
    m.w = fmaxf(m.w, b.y);
}

__global__ __launch_bounds__(256) void agg_fused_kernel(
    const __half* __restrict__ tmp, const int* __restrict__ off,
    const int* __restrict__ csr, const __half* __restrict__ root16,
    __half* __restrict__ h16)
{
    int node = blockIdx.x * 8 + (threadIdx.x >> 5);
    if (node >= N_NODES) return;
    int lane = threadIdx.x & 31;
    size_t base = (size_t)node * EMB + lane * 4;

    int s[N_REL], e[N_REL];
#pragma unroll
    for (int r = 0; r < N_REL; r++) {
        const int* offr = off + (size_t)r * (N_NODES + 1);
        s[r] = __ldg(&offr[node]);
        e[r] = __ldg(&offr[node + 1]);
    }

    uint2 ru = __ldcs((const uint2*)(root16 + base));
    float2 ra = __half22float2(*(__half2*)&ru.x);
    float2 rb = __half22float2(*(__half2*)&ru.y);
    float4 acc = make_float4(ra.x, ra.y, rb.x, rb.y);

#pragma unroll
    for (int r = 0; r < N_REL; r++) {
        int i = s[r], ecnt = e[r];
        if (i >= ecnt) continue;
        const int* csrr = csr + (size_t)r * N_EDGES;
        const __half* msg = tmp + (size_t)r * (size_t)N_NODES * EMB;
        float4 m = make_float4(-FLT_MAX, -FLT_MAX, -FLT_MAX, -FLT_MAX);
        for (; i + 3 < ecnt; i += 4) {
            int s0 = __ldg(&csrr[i]);
            int s1 = __ldg(&csrr[i + 1]);
            int s2i = __ldg(&csrr[i + 2]);
            int s3 = __ldg(&csrr[i + 3]);
            fmax4(m, msg, s0, lane);
            fmax4(m, msg, s1, lane);
            fmax4(m, msg, s2i, lane);
            fmax4(m, msg, s3, lane);
        }
        if (i + 1 < ecnt) {
            int s0 = __ldg(&csrr[i]);
            int s1 = __ldg(&csrr[i + 1]);
            fmax4(m, msg, s0, lane);
            fmax4(m, msg, s1, lane);
            i += 2;
        }
        if (i < ecnt) {
            int s0 = __ldg(&csrr[i]);
            fmax4(m, msg, s0, lane);
        }
        acc.x += m.x; acc.y += m.y; acc.z += m.z; acc.w += m.w;
    }

    acc.x = fmaxf(acc.x, 0.0f);
    acc.y = fmaxf(acc.y, 0.0f);
    acc.z = fmaxf(acc.z, 0.0f);
    acc.w = fmaxf(acc.w, 0.0f);

    *(__half2*)(h16 + base) = __floats2half2_rn(acc.x, acc.y);
    *(__half2*)(h16 + base + 2) = __floats2half2_rn(acc.z, acc.w);
}

// ---------------- global add pool (reads fp16 h, fp32 accumulate) ----------------
__global__ __launch_bounds__(128) void pool_kernel(
    const __half* __restrict__ h16, const int* __restrict__ batch,
    float* __restrict__ out, int n)
{
    const int NPB = 256;
    int f = threadIdx.x;
    int n0 = blockIdx.x * NPB;
    if (n0 >= n) return;
    int nend = min(n0 + NPB, n);
    float acc = 0.0f;
    int cur = batch[n0];
    for (int i = n0; i < nend; i++) {
        int b = batch[i];
        if (b != cur) {
            atomicAdd(&out[(size_t)cur * EMB + f], acc);
            acc = 0.0f;
            cur = b;
        }
        acc += __half2float(h16[(size_t)i * EMB + f]);
    }
    atomicAdd(&out[(size_t)cur * EMB + f], acc);
}

// ---------------- host launch ----------------
extern "C" void kernel_launch(void* const* d_in, const int* in_sizes, int n_in,
                              void* d_out, int out_size)
{
    const float* x      = (const float*)d_in[0];
    const int*   e0     = (const int*)d_in[1];
    const int*   e1     = (const int*)d_in[2];
    const int*   e2     = (const int*)d_in[3];
    const int*   e3     = (const int*)d_in[4];
    const int*   batch  = (const int*)d_in[5];
    const float* emb_w  = (const float*)d_in[6];
    const float* emb_b  = (const float*)d_in[7];
    const float* root_w = (const float*)d_in[8];
    const float* root_b = (const float*)d_in[9];
    const float* conv_w = (const float*)d_in[10];
    float* out = (float*)d_out;

    void *p_out16, *p_tmp, *p_h16, *p_x16, *p_w16;
    void *p_csr, *p_deg, *p_off, *p_cur, *p_bsum;
    cudaGetSymbolAddress(&p_out16, g_out16);
    cudaGetSymbolAddress(&p_tmp, g_tmp);
    cudaGetSymbolAddress(&p_h16, g_h16);
    cudaGetSymbolAddress(&p_x16, g_x16);
    cudaGetSymbolAddress(&p_w16, g_w16);
    cudaGetSymbolAddress(&p_csr, g_csr_src);
    cudaGetSymbolAddress(&p_deg, g_deg);
    cudaGetSymbolAddress(&p_off, g_off);
    cudaGetSymbolAddress(&p_cur, g_cur);
    cudaGetSymbolAddress(&p_bsum, g_bsum);
    __half* out16 = (__half*)p_out16;
    __half* tmp  = (__half*)p_tmp;
    __half* h16  = (__half*)p_h16;
    __half* x16  = (__half*)p_x16;
    __half* w16  = (__half*)p_w16;
    int* csr = (int*)p_csr;
    int* deg = (int*)p_deg;
    int* off = (int*)p_off;
    int* cur = (int*)p_cur;
    int* bsum = (int*)p_bsum;

    static bool attr_set = []() {
        cudaFuncSetAttribute(gemm_mma, cudaFuncAttributeMaxDynamicSharedMemorySize, GEMM_SMEM);
        return true;
    }();
    (void)attr_set;

    static cudaStream_t s2 = []() {
        cudaStream_t s;
        cudaStreamCreateWithFlags(&s, cudaStreamNonBlocking);
        return s;
    }();
    static cudaEvent_t evFork = []() {
        cudaEvent_t e; cudaEventCreateWithFlags(&e, cudaEventDisableTiming); return e;
    }();
    static cudaEvent_t evCsr = []() {
        cudaEvent_t e; cudaEventCreateWithFlags(&e, cudaEventDisableTiming); return e;
    }();

    const int EB = (N_EDGES + 255) / 256;
    const int GB = (N_NODES + 127) / 128;
    const int AB = (N_NODES + 7) / 8;

    // ---- fork CSR build to s2 (overlaps with conversions + embed GEMM) ----
    cudaEventRecord(evFork, 0);
    cudaStreamWaitEvent(s2, evFork, 0);
    zero_int_kernel<<<(N_REL * N_NODES + 255) / 256, 256, 0, s2>>>(deg, N_REL * N_NODES);
    hist_all_kernel<<<dim3(EB, N_REL), 256, 0, s2>>>(e0, e1, e2, e3, deg);
    scan_p1<<<dim3(SCAN_NB, N_REL), 256, 0, s2>>>(deg, bsum);
    scan_p2<<<1, 512, 0, s2>>>(bsum);
    scan_p3<<<dim3(SCAN_NB, N_REL), 256, 0, s2>>>(deg, bsum, off, cur);
    fill_all_kernel<<<dim3(EB, N_REL), 256, 0, s2>>>(e0, e1, e2, e3, cur, csr);
    cudaEventRecord(evCsr, s2);

    // ---- main stream: conversions + embed ----
    conv_w_kernel<<<(21 * 128 * 128 + 255) / 256, 256>>>(emb_w, root_w, conv_w, w16);
    conv_x_kernel<<<(N_NODES * IN_FEAT + 255) / 256, 256>>>(x, x16, N_NODES * IN_FEAT);
    gemm_mma<<<dim3(GB, 1), 256, GEMM_SMEM>>>(x16, N_NODES, IN_FEAT, w16,
                                              /*slotArg=*/0, /*mode=*/2, emb_b,
                                              h16, (__half*)0);

    bool joined = false;
    for (int l = 0; l < N_LAYERS; l++) {
        int slotArg = ((1 + l) << 16) | (4 + 4 * l);
        gemm_mma<<<dim3(GB, 5), 256, GEMM_SMEM>>>(h16, N_NODES, EMB, w16,
                                                  slotArg, /*mode=*/1,
                                                  root_b + (size_t)l * EMB,
                                                  out16, tmp);
        if (!joined) {
            cudaStreamWaitEvent(0, evCsr, 0);
            joined = true;
        }
        agg_fused_kernel<<<AB, 256>>>(tmp, off, csr, out16, h16);
    }

    // ---- global add pool ----
    zero_float_kernel<<<(N_GRAPHS * EMB + 255) / 256, 256>>>(out, N_GRAPHS * EMB);
    pool_kernel<<<(N_NODES + 255) / 256, 128>>>(h16, batch, out, N_NODES);
}

// round 15
// speedup vs baseline: 1.0588x; 1.0588x over previous
#include <cuda_runtime.h>
#include <cuda_fp16.h>
#include <cstdint>
#include <cfloat>

#define N_NODES 100000
#define N_EDGES 500000
#define N_REL 4
#define N_LAYERS 4
#define IN_FEAT 64
#define EMB 128
#define N_GRAPHS 64
#define SCAN_NB 98   // ceil(100000/1024)

// ---------------- scratch (device globals; no allocation allowed) ----------------
__device__ __half g_out16[(size_t)N_NODES * EMB];        // root accumulator fp16
__device__ __half g_tmp[(size_t)2 * N_NODES * EMB];      // 2 conv output buffers (one array!)
__device__ __half g_h16[(size_t)N_NODES * EMB];          // h fp16 (GEMM A / pool input)
// 21 weight matrices, transposed [N=128][K=128] fp16:
// slot 0 = emb (K rows 64..127 zero), 1..4 = root, 5..20 = conv (l*4+r)
__device__ __half g_w16[(size_t)21 * 128 * 128];
__device__ int   g_csr_src[(size_t)N_REL * N_EDGES];
__device__ int   g_deg[(size_t)N_REL * N_NODES];
__device__ int   g_off[(size_t)N_REL * (N_NODES + 1)];
__device__ int   g_cur[(size_t)N_REL * N_NODES];
__device__ int   g_bsum[(size_t)N_REL * 128];

// ---------------- helpers ----------------
__device__ __forceinline__ uint32_t smem_u32(const void* p) {
    uint32_t a;
    asm("{ .reg .u64 t; cvta.to.shared.u64 t, %1; cvt.u32.u64 %0, t; }" : "=r"(a) : "l"(p));
    return a;
}
__device__ __forceinline__ void ldsm4(uint32_t& r0, uint32_t& r1, uint32_t& r2, uint32_t& r3,
                                      uint32_t addr) {
    asm volatile("ldmatrix.sync.aligned.m8n8.x4.shared.b16 {%0,%1,%2,%3}, [%4];"
                 : "=r"(r0), "=r"(r1), "=r"(r2), "=r"(r3) : "r"(addr));
}
__device__ __forceinline__ void mma16816(float* d, const uint32_t* a, const uint32_t* b) {
    asm volatile(
        "mma.sync.aligned.m16n8k16.row.col.f32.f16.f16.f32 "
        "{%0,%1,%2,%3}, {%4,%5,%6,%7}, {%8,%9}, {%0,%1,%2,%3};"
        : "+f"(d[0]), "+f"(d[1]), "+f"(d[2]), "+f"(d[3])
        : "r"(a[0]), "r"(a[1]), "r"(a[2]), "r"(a[3]), "r"(b[0]), "r"(b[1]));
}
#define CP_ASYNC16(dst, src, n) \
    asm volatile("cp.async.ca.shared.global [%0], [%1], 16, %2;" \
                 :: "r"(dst), "l"(src), "r"(n))

// ---------------- utility kernels ----------------
__global__ void zero_int_kernel(int* p, int n) {
    int i = blockIdx.x * blockDim.x + threadIdx.x;
    if (i < n) p[i] = 0;
}
__global__ void zero_float_kernel(float* p, int n) {
    int i = blockIdx.x * blockDim.x + threadIdx.x;
    if (i < n) p[i] = 0.0f;
}

__global__ void hist_all_kernel(const int* __restrict__ e0, const int* __restrict__ e1,
                                const int* __restrict__ e2, const int* __restrict__ e3,
                                int* __restrict__ deg) {
    int r = blockIdx.y;
    const int* dst = ((r == 0) ? e0 : (r == 1) ? e1 : (r == 2) ? e2 : e3) + N_EDGES;
    int i = blockIdx.x * 256 + threadIdx.x;
    if (i < N_EDGES) atomicAdd(&deg[(size_t)r * N_NODES + dst[i]], 1);
}

// -------- 3-phase parallel exclusive scan of deg -> off (all relations) --------
__global__ void scan_p1(const int* __restrict__ deg, int* __restrict__ bsum) {
    int r = blockIdx.y, b = blockIdx.x, t = threadIdx.x;
    const int* d = deg + (size_t)r * N_NODES;
    int base = b * 1024 + t * 4;
    int s = 0;
#pragma unroll
    for (int j = 0; j < 4; j++) {
        int idx = base + j;
        if (idx < N_NODES) s += d[idx];
    }
    __shared__ int sm[256];
    sm[t] = s;
    __syncthreads();
    for (int o = 128; o > 0; o >>= 1) {
        if (t < o) sm[t] += sm[t + o];
        __syncthreads();
    }
    if (t == 0) bsum[r * 128 + b] = sm[0];
}
__global__ void scan_p2(int* __restrict__ bsum) {
    __shared__ int sm[512];
    int t = threadIdx.x;
    int r = t >> 7;
    int i = t & 127;
    int v = (i < SCAN_NB) ? bsum[r * 128 + i] : 0;
    sm[t] = v;
    __syncthreads();
    for (int d = 1; d < 128; d <<= 1) {
        int add = (i >= d) ? sm[t - d] : 0;
        __syncthreads();
        sm[t] += add;
        __syncthreads();
    }
    int excl = (i == 0) ? 0 : sm[t - 1];
    if (i < SCAN_NB) bsum[r * 128 + i] = excl;
}
__global__ void scan_p3(const int* __restrict__ deg, const int* __restrict__ bsum,
                        int* __restrict__ off, int* __restrict__ cur) {
    int r = blockIdx.y, b = blockIdx.x, t = threadIdx.x;
    const int* d = deg + (size_t)r * N_NODES;
    int* o = off + (size_t)r * (N_NODES + 1);
    int* c = cur + (size_t)r * N_NODES;
    int base = b * 1024 + t * 4;
    int v[4], pre[4];
    int s = 0;
#pragma unroll
    for (int j = 0; j < 4; j++) {
        int idx = base + j;
        v[j] = (idx < N_NODES) ? d[idx] : 0;
        pre[j] = s;
        s += v[j];
    }
    __shared__ int sm[256];
    sm[t] = s;
    __syncthreads();
    for (int dd = 1; dd < 256; dd <<= 1) {
        int add = (t >= dd) ? sm[t - dd] : 0;
        __syncthreads();
        sm[t] += add;
        __syncthreads();
    }
    int texcl = (t == 0) ? 0 : sm[t - 1];
    int boff = bsum[r * 128 + b];
#pragma unroll
    for (int j = 0; j < 4; j++) {
        int idx = base + j;
        if (idx < N_NODES) {
            int val = boff + texcl + pre[j];
            o[idx] = val;
            c[idx] = val;
        }
    }
    if (b == SCAN_NB - 1 && t == 255) o[N_NODES] = boff + sm[255];
}

__global__ void fill_all_kernel(const int* __restrict__ e0, const int* __restrict__ e1,
                                const int* __restrict__ e2, const int* __restrict__ e3,
                                int* __restrict__ cur, int* __restrict__ csr) {
    int r = blockIdx.y;
    const int* eptr = (r == 0) ? e0 : (r == 1) ? e1 : (r == 2) ? e2 : e3;
    int i = blockIdx.x * 256 + threadIdx.x;
    if (i < N_EDGES) {
        int dnode = eptr[N_EDGES + i];
        int pos = atomicAdd(&cur[(size_t)r * N_NODES + dnode], 1);
        csr[(size_t)r * N_EDGES + pos] = eptr[i];
    }
}

// ---------------- weight conversion ----------------
__global__ void conv_w_kernel(const float* __restrict__ emb_w,
                              const float* __restrict__ root_w,
                              const float* __restrict__ conv_w,
                              __half* __restrict__ w16) {
    int idx = blockIdx.x * blockDim.x + threadIdx.x;
    if (idx >= 21 * 128 * 128) return;
    int s = idx >> 14;
    int rem = idx & 16383;
    int n = rem >> 7;
    int k = rem & 127;
    float v;
    if (s == 0)      v = (k < IN_FEAT) ? emb_w[(size_t)k * EMB + n] : 0.0f;
    else if (s <= 4) v = root_w[((size_t)(s - 1) * EMB + k) * EMB + n];
    else             v = conv_w[((size_t)(s - 5) * EMB + k) * EMB + n];
    w16[idx] = __float2half(v);
}

// ---------------- shared GEMM constants ----------------
#define BK 32
#define SSTR 40
#define BSTR 136
#define ASTR_E 72                            // embed A smem row stride (halves)
#define A_TILE_B (128 * SSTR * 2)            // 10240
#define B_TILE_B (128 * BSTR * 2)            // 34816
#define GEMM_SMEM (B_TILE_B + 2 * A_TILE_B)  // 55296 (layer kernel)
#define EMBED_SMEM (B_TILE_B + 128 * ASTR_E * 2)  // 34816 + 18432 = 53248

// ---------------- fp16 layer GEMM: 2-stage cp.async A, B preload ----------------
// rootFlag==1: y0 -> root slot (slotArg>>16) -> dst0 fp16 + bias; y>=1 conv
//   slot (slotArg&0xFFFF)+y -> tmp + (y-1)*MN.
// rootFlag==0: y -> conv slot (slotArg&0xFFFF)+y -> tmp + y*MN.
__global__ __launch_bounds__(256, 2) void gemm_layer16(
    const __half* __restrict__ A, int M,
    const __half* __restrict__ w_base, int slotArg, int rootFlag,
    const float* __restrict__ bias0,
    __half* __restrict__ dst0, __half* __restrict__ tmp)
{
    const int K = EMB;
    extern __shared__ __half sm_dyn[];
    uint32_t bs_u = smem_u32(sm_dyn);
    uint32_t as_u = bs_u + B_TILE_B;

    int y = blockIdx.y;
    int slot = (rootFlag && y == 0) ? (slotArg >> 16) : ((slotArg & 0xFFFF) + y);
    const __half* W = w_base + (size_t)slot * 16384;

    int tid = threadIdx.x;
    int wid = tid >> 5;
    int lane = tid & 31;
    int wm = wid & 1;
    int wn = wid >> 1;
    int r0 = blockIdx.x * 128;

    // ---- preload B (full 128x128) into smem ----
    for (int idx = tid; idx < 2048; idx += 256) {
        int row = idx >> 4;
        int ch = idx & 15;
        uint32_t soff = (uint32_t)(row * BSTR + ch * 8) * 2u;
        CP_ASYNC16(bs_u + soff,
                   (uint64_t)__cvta_generic_to_global(W + (size_t)row * 128 + ch * 8), 16);
    }
    asm volatile("cp.async.commit_group;");

    float acc[4][4][4];
#pragma unroll
    for (int i = 0; i < 4; i++)
#pragma unroll
        for (int j = 0; j < 4; j++)
#pragma unroll
            for (int q = 0; q < 4; q++) acc[i][j][q] = 0.0f;

    int l_within = lane & 7;
    int l_sel = lane >> 3;
    const int nch = K >> 5;   // 4

    int li0 = tid * 2, li1 = tid * 2 + 1;
    int lr0 = li0 >> 2, lc0 = li0 & 3;
    int lr1 = li1 >> 2, lc1 = li1 & 3;

    auto load_stage = [&](int kc, int st) {
        int k0 = kc * BK;
#pragma unroll
        for (int i = 0; i < 2; i++) {
            int row = i ? lr1 : lr0;
            int ch  = i ? lc1 : lc0;
            int gr = r0 + row;
            int ok = (gr < M) ? 16 : 0;
            int grc = (gr < M) ? gr : 0;
            uint32_t soff = (uint32_t)(row * SSTR + ch * 8) * 2u;
            CP_ASYNC16(as_u + (uint32_t)st * A_TILE_B + soff,
                       (uint64_t)__cvta_generic_to_global(A + (size_t)grc * K + k0 + ch * 8), ok);
        }
        asm volatile("cp.async.commit_group;");
    };

    load_stage(0, 0);
    for (int kc = 0; kc < nch; kc++) {
        int st = kc & 1;
        if (kc + 1 < nch) {
            load_stage(kc + 1, st ^ 1);
            asm volatile("cp.async.wait_group 1;");
        } else {
            asm volatile("cp.async.wait_group 0;");
        }
        __syncthreads();

        uint32_t a_stage = as_u + (uint32_t)st * A_TILE_B;
#pragma unroll
        for (int ks = 0; ks < 2; ks++) {
            uint32_t af[4][4];
            uint32_t bf[4][2];
#pragma unroll
            for (int fm = 0; fm < 4; fm++) {
                int arow = wm * 64 + fm * 16 + (l_sel & 1) * 8 + l_within;
                int acol = ks * 16 + (l_sel >> 1) * 8;
                ldsm4(af[fm][0], af[fm][1], af[fm][2], af[fm][3],
                      a_stage + (uint32_t)(arow * SSTR + acol) * 2u);
            }
#pragma unroll
            for (int g = 0; g < 2; g++) {
                int brow = wn * 32 + g * 16 + (l_sel >> 1) * 8 + l_within;
                int bcol = kc * 32 + ks * 16 + (l_sel & 1) * 8;
                uint32_t r0v, r1v, r2v, r3v;
                ldsm4(r0v, r1v, r2v, r3v,
                      bs_u + (uint32_t)(brow * BSTR + bcol) * 2u);
                bf[2 * g + 0][0] = r0v; bf[2 * g + 0][1] = r1v;
                bf[2 * g + 1][0] = r2v; bf[2 * g + 1][1] = r3v;
            }
#pragma unroll
            for (int fm = 0; fm < 4; fm++)
#pragma unroll
                for (int fn = 0; fn < 4; fn++)
                    mma16816(acc[fm][fn], af[fm], bf[fn]);
        }
        __syncthreads();
    }

    // ---- epilogue (fp16 outputs) ----
    int qrow = lane >> 2;
    int qcol = (lane & 3) * 2;
    bool is_root = (rootFlag && y == 0);
    int cidx = rootFlag ? (y - 1) : y;
    __half* dst = is_root ? dst0 : (tmp + (size_t)cidx * (size_t)N_NODES * EMB);
#pragma unroll
    for (int fm = 0; fm < 4; fm++) {
#pragma unroll
        for (int half_i = 0; half_i < 2; half_i++) {
            int grow = r0 + wm * 64 + fm * 16 + qrow + half_i * 8;
            if (grow >= M) continue;
#pragma unroll
            for (int fn = 0; fn < 4; fn++) {
                int col = wn * 32 + fn * 8 + qcol;
                float v0 = acc[fm][fn][half_i * 2 + 0];
                float v1 = acc[fm][fn][half_i * 2 + 1];
                if (is_root) {
                    v0 += __ldg(&bias0[col]);
                    v1 += __ldg(&bias0[col + 1]);
                }
                *(__half2*)(dst + (size_t)grow * EMB + col) = __floats2half2_rn(v0, v1);
            }
        }
    }
}

// ---------------- embed GEMM: fp32 A loaded + converted in-kernel (K=64) ----------------
__global__ __launch_bounds__(256, 2) void gemm_embed(
    const float* __restrict__ x, int M,
    const __half* __restrict__ w_base,
    const float* __restrict__ bias,
    __half* __restrict__ h16)
{
    const int K = IN_FEAT;   // 64
    extern __shared__ __half sm_dyn[];
    uint32_t bs_u = smem_u32(sm_dyn);
    __half* As = sm_dyn + B_TILE_B / 2;      // B_TILE_B bytes offset (halves ptr)

    const __half* W = w_base;                // slot 0

    int tid = threadIdx.x;
    int wid = tid >> 5;
    int lane = tid & 31;
    int wm = wid & 1;
    int wn = wid >> 1;
    int r0 = blockIdx.x * 128;

    // ---- preload B ----
    for (int idx = tid; idx < 2048; idx += 256) {
        int row = idx >> 4;
        int ch = idx & 15;
        uint32_t soff = (uint32_t)(row * BSTR + ch * 8) * 2u;
        CP_ASYNC16(bs_u + soff,
                   (uint64_t)__cvta_generic_to_global(W + (size_t)row * 128 + ch * 8), 16);
    }
    asm volatile("cp.async.commit_group;");

    // ---- load A (fp32 -> fp16 convert) full tile: 128 rows x 64 cols ----
    for (int c = 0; c < 4; c++) {
        int idx = tid + c * 256;
        int row = idx >> 3;
        int ch = idx & 7;
        int gr = r0 + row;
        __half2 h2[4];
        if (gr < M) {
            const float4* px = (const float4*)(x + (size_t)gr * K + ch * 8);
            float4 f0 = px[0];
            float4 f1 = px[1];
            h2[0] = __floats2half2_rn(f0.x, f0.y);
            h2[1] = __floats2half2_rn(f0.z, f0.w);
            h2[2] = __floats2half2_rn(f1.x, f1.y);
            h2[3] = __floats2half2_rn(f1.z, f1.w);
        } else {
            h2[0] = h2[1] = h2[2] = h2[3] = __floats2half2_rn(0.f, 0.f);
        }
        *(uint4*)(As + row * ASTR_E + ch * 8) = *(uint4*)h2;
    }
    asm volatile("cp.async.wait_group 0;");
    __syncthreads();

    float acc[4][4][4];
#pragma unroll
    for (int i = 0; i < 4; i++)
#pragma unroll
        for (int j = 0; j < 4; j++)
#pragma unroll
            for (int q = 0; q < 4; q++) acc[i][j][q] = 0.0f;

    int l_within = lane & 7;
    int l_sel = lane >> 3;
    uint32_t as_base = smem_u32(As);

    for (int kc = 0; kc < 2; kc++) {
#pragma unroll
        for (int ks = 0; ks < 2; ks++) {
            uint32_t af[4][4];
            uint32_t bf[4][2];
#pragma unroll
            for (int fm = 0; fm < 4; fm++) {
                int arow = wm * 64 + fm * 16 + (l_sel & 1) * 8 + l_within;
                int acol = kc * 32 + ks * 16 + (l_sel >> 1) * 8;
                ldsm4(af[fm][0], af[fm][1], af[fm][2], af[fm][3],
                      as_base + (uint32_t)(arow * ASTR_E + acol) * 2u);
            }
#pragma unroll
            for (int g = 0; g < 2; g++) {
                int brow = wn * 32 + g * 16 + (l_sel >> 1) * 8 + l_within;
                int bcol = kc * 32 + ks * 16 + (l_sel & 1) * 8;
                uint32_t r0v, r1v, r2v, r3v;
                ldsm4(r0v, r1v, r2v, r3v,
                      bs_u + (uint32_t)(brow * BSTR + bcol) * 2u);
                bf[2 * g + 0][0] = r0v; bf[2 * g + 0][1] = r1v;
                bf[2 * g + 1][0] = r2v; bf[2 * g + 1][1] = r3v;
            }
#pragma unroll
            for (int fm = 0; fm < 4; fm++)
#pragma unroll
                for (int fn = 0; fn < 4; fn++)
                    mma16816(acc[fm][fn], af[fm], bf[fn]);
        }
    }

    int qrow = lane >> 2;
    int qcol = (lane & 3) * 2;
#pragma unroll
    for (int fm = 0; fm < 4; fm++) {
#pragma unroll
        for (int half_i = 0; half_i < 2; half_i++) {
            int grow = r0 + wm * 64 + fm * 16 + qrow + half_i * 8;
            if (grow >= M) continue;
#pragma unroll
            for (int fn = 0; fn < 4; fn++) {
                int col = wn * 32 + fn * 8 + qcol;
                float v0 = acc[fm][fn][half_i * 2 + 0] + __ldg(&bias[col]);
                float v1 = acc[fm][fn][half_i * 2 + 1] + __ldg(&bias[col + 1]);
                *(__half2*)(h16 + (size_t)grow * EMB + col) = __floats2half2_rn(v0, v1);
            }
        }
    }
}

// ---------------- pair-fused aggregation (warp per node, fp16) ----------------
__device__ __forceinline__ void agg_one_rel16(
    const __half* __restrict__ msg, const int* __restrict__ off,
    const int* __restrict__ csr, int node, int lane, float4& acc)
{
    int s = __ldg(&off[node]);
    int e = __ldg(&off[node + 1]);
    if (s >= e) return;
    float4 m = make_float4(-FLT_MAX, -FLT_MAX, -FLT_MAX, -FLT_MAX);
    int i = s;
    for (; i + 1 < e; i += 2) {
        int s0 = __ldg(&csr[i]);
        int s1 = __ldg(&csr[i + 1]);
        uint2 u0 = *(const uint2*)(msg + (size_t)s0 * EMB + lane * 4);
        uint2 u1 = *(const uint2*)(msg + (size_t)s1 * EMB + lane * 4);
        float2 a0 = __half22float2(*(__half2*)&u0.x);
        float2 b0 = __half22float2(*(__half2*)&u0.y);
        float2 a1 = __half22float2(*(__half2*)&u1.x);
        float2 b1 = __half22float2(*(__half2*)&u1.y);
        m.x = fmaxf(m.x, fmaxf(a0.x, a1.x));
        m.y = fmaxf(m.y, fmaxf(a0.y, a1.y));
        m.z = fmaxf(m.z, fmaxf(b0.x, b1.x));
        m.w = fmaxf(m.w, fmaxf(b0.y, b1.y));
    }
    if (i < e) {
        int s0 = __ldg(&csr[i]);
        uint2 u0 = *(const uint2*)(msg + (size_t)s0 * EMB + lane * 4);
        float2 a0 = __half22float2(*(__half2*)&u0.x);
        float2 b0 = __half22float2(*(__half2*)&u0.y);
        m.x = fmaxf(m.x, a0.x);
        m.y = fmaxf(m.y, a0.y);
        m.z = fmaxf(m.z, b0.x);
        m.w = fmaxf(m.w, b0.y);
    }
    acc.x += m.x; acc.y += m.y; acc.z += m.z; acc.w += m.w;
}

__global__ __launch_bounds__(256) void agg_pair_kernel(
    const __half* __restrict__ msg0, const __half* __restrict__ msg1,
    const int* __restrict__ off0, const int* __restrict__ csr0,
    const int* __restrict__ off1, const int* __restrict__ csr1,
    __half* __restrict__ out16, __half* __restrict__ h16,
    int last)
{
    int node = blockIdx.x * 8 + (threadIdx.x >> 5);
    if (node >= N_NODES) return;
    int lane = threadIdx.x & 31;
    size_t base = (size_t)node * EMB + lane * 4;

    uint2 ru = __ldcs((const uint2*)(out16 + base));
    float2 ra = __half22float2(*(__half2*)&ru.x);
    float2 rb = __half22float2(*(__half2*)&ru.y);
    float4 acc = make_float4(ra.x, ra.y, rb.x, rb.y);

    agg_one_rel16(msg0, off0, csr0, node, lane, acc);
    agg_one_rel16(msg1, off1, csr1, node, lane, acc);

    if (!last) {
        __half2 p0 = __floats2half2_rn(acc.x, acc.y);
        __half2 p1 = __floats2half2_rn(acc.z, acc.w);
        uint2 uo; uo.x = *(uint32_t*)&p0; uo.y = *(uint32_t*)&p1;
        __stcs((uint2*)(out16 + base), uo);
        return;
    }

    acc.x = fmaxf(acc.x, 0.0f);
    acc.y = fmaxf(acc.y, 0.0f);
    acc.z = fmaxf(acc.z, 0.0f);
    acc.w = fmaxf(acc.w, 0.0f);
    *(__half2*)(h16 + base) = __floats2half2_rn(acc.x, acc.y);
    *(__half2*)(h16 + base + 2) = __floats2half2_rn(acc.z, acc.w);
}

// ---------------- global add pool (reads fp16 h, fp32 accumulate) ----------------
__global__ __launch_bounds__(128) void pool_kernel(
    const __half* __restrict__ h16, const int* __restrict__ batch,
    float* __restrict__ out, int n)
{
    const int NPB = 256;
    int f = threadIdx.x;
    int n0 = blockIdx.x * NPB;
    if (n0 >= n) return;
    int nend = min(n0 + NPB, n);
    float acc = 0.0f;
    int cur = batch[n0];
    for (int i = n0; i < nend; i++) {
        int b = batch[i];
        if (b != cur) {
            atomicAdd(&out[(size_t)cur * EMB + f], acc);
            acc = 0.0f;
            cur = b;
        }
        acc += __half2float(h16[(size_t)i * EMB + f]);
    }
    atomicAdd(&out[(size_t)cur * EMB + f], acc);
}

// ---------------- host launch ----------------
extern "C" void kernel_launch(void* const* d_in, const int* in_sizes, int n_in,
                              void* d_out, int out_size)
{
    const float* x      = (const float*)d_in[0];
    const int*   e0     = (const int*)d_in[1];
    const int*   e1     = (const int*)d_in[2];
    const int*   e2     = (const int*)d_in[3];
    const int*   e3     = (const int*)d_in[4];
    const int*   batch  = (const int*)d_in[5];
    const float* emb_w  = (const float*)d_in[6];
    const float* emb_b  = (const float*)d_in[7];
    const float* root_w = (const float*)d_in[8];
    const float* root_b = (const float*)d_in[9];
    const float* conv_w = (const float*)d_in[10];
    float* out = (float*)d_out;

    void *p_out16, *p_tmp, *p_h16, *p_w16;
    void *p_csr, *p_deg, *p_off, *p_cur, *p_bsum;
    cudaGetSymbolAddress(&p_out16, g_out16);
    cudaGetSymbolAddress(&p_tmp, g_tmp);
    cudaGetSymbolAddress(&p_h16, g_h16);
    cudaGetSymbolAddress(&p_w16, g_w16);
    cudaGetSymbolAddress(&p_csr, g_csr_src);
    cudaGetSymbolAddress(&p_deg, g_deg);
    cudaGetSymbolAddress(&p_off, g_off);
    cudaGetSymbolAddress(&p_cur, g_cur);
    cudaGetSymbolAddress(&p_bsum, g_bsum);
    __half* out16 = (__half*)p_out16;
    __half* tmp  = (__half*)p_tmp;
    __half* h16  = (__half*)p_h16;
    __half* w16  = (__half*)p_w16;
    int* csr = (int*)p_csr;
    int* deg = (int*)p_deg;
    int* off = (int*)p_off;
    int* cur = (int*)p_cur;
    int* bsum = (int*)p_bsum;

    const size_t MN = (size_t)N_NODES * EMB;

    static bool attr_set = []() {
        cudaFuncSetAttribute(gemm_layer16, cudaFuncAttributeMaxDynamicSharedMemorySize, GEMM_SMEM);
        cudaFuncSetAttribute(gemm_embed, cudaFuncAttributeMaxDynamicSharedMemorySize, EMBED_SMEM);
        return true;
    }();
    (void)attr_set;

    static cudaStream_t s2 = []() {
        cudaStream_t s;
        cudaStreamCreateWithFlags(&s, cudaStreamNonBlocking);
        return s;
    }();
    static cudaEvent_t evFork = []() {
        cudaEvent_t e; cudaEventCreateWithFlags(&e, cudaEventDisableTiming); return e;
    }();
    static cudaEvent_t evCsr = []() {
        cudaEvent_t e; cudaEventCreateWithFlags(&e, cudaEventDisableTiming); return e;
    }();

    const int EB = (N_EDGES + 255) / 256;
    const int GB = (N_NODES + 127) / 128;
    const int AB = (N_NODES + 7) / 8;

    // ---- fork CSR build to s2 (overlaps with weight conversion + embed GEMM) ----
    cudaEventRecord(evFork, 0);
    cudaStreamWaitEvent(s2, evFork, 0);
    zero_int_kernel<<<(N_REL * N_NODES + 255) / 256, 256, 0, s2>>>(deg, N_REL * N_NODES);
    hist_all_kernel<<<dim3(EB, N_REL), 256, 0, s2>>>(e0, e1, e2, e3, deg);
    scan_p1<<<dim3(SCAN_NB, N_REL), 256, 0, s2>>>(deg, bsum);
    scan_p2<<<1, 512, 0, s2>>>(bsum);
    scan_p3<<<dim3(SCAN_NB, N_REL), 256, 0, s2>>>(deg, bsum, off, cur);
    fill_all_kernel<<<dim3(EB, N_REL), 256, 0, s2>>>(e0, e1, e2, e3, cur, csr);
    cudaEventRecord(evCsr, s2);

    // ---- main stream: weight convert + embed (fp32 x consumed directly) ----
    conv_w_kernel<<<(21 * 128 * 128 + 255) / 256, 256>>>(emb_w, root_w, conv_w, w16);
    gemm_embed<<<GB, 256, EMBED_SMEM>>>(x, N_NODES, w16, emb_b, h16);

    bool joined = false;
    for (int l = 0; l < N_LAYERS; l++) {
        // root + conv0 + conv1: y0 root -> out16, y1 -> tmp[0], y2 -> tmp[MN]
        int slotArg1 = ((1 + l) << 16) | (4 + 4 * l);   // y1->5+4l, y2->6+4l
        gemm_layer16<<<dim3(GB, 3), 256, GEMM_SMEM>>>(h16, N_NODES, w16,
                                                      slotArg1, /*rootFlag=*/1,
                                                      root_b + (size_t)l * EMB,
                                                      out16, tmp);
        if (!joined) {
            cudaStreamWaitEvent(0, evCsr, 0);
            joined = true;
        }
        agg_pair_kernel<<<AB, 256>>>(tmp, tmp + MN,
                                     off, csr,
                                     off + (size_t)(N_NODES + 1), csr + (size_t)N_EDGES,
                                     out16, h16, 0);
        // conv2 + conv3: y0 -> tmp[0], y1 -> tmp[MN] (reuse, L2-hot)
        int slotArg2 = 7 + 4 * l;                        // y0->7+4l, y1->8+4l
        gemm_layer16<<<dim3(GB, 2), 256, GEMM_SMEM>>>(h16, N_NODES, w16,
                                                      slotArg2, /*rootFlag=*/0,
                                                      (const float*)0,
                                                      (__half*)0, tmp);
        agg_pair_kernel<<<AB, 256>>>(tmp, tmp + MN,
                                     off + (size_t)2 * (N_NODES + 1), csr + (size_t)2 * N_EDGES,
                                     off + (size_t)3 * (N_NODES + 1), csr + (size_t)3 * N_EDGES,
                                     out16, h16, 1);
    }

    // ---- global add pool ----
    zero_float_kernel<<<(N_GRAPHS * EMB + 255) / 256, 256>>>(out, N_GRAPHS * EMB);
    pool_kernel<<<(N_NODES + 255) / 256, 128>>>(h16, batch, out, N_NODES);
}

// round 16
// speedup vs baseline: 1.0718x; 1.0122x over previous
#include <cuda_runtime.h>
#include <cuda_fp16.h>
#include <cstdint>
#include <cfloat>

#define N_NODES 100000
#define N_EDGES 500000
#define N_REL 4
#define N_LAYERS 4
#define IN_FEAT 64
#define EMB 128
#define N_GRAPHS 64
#define SCAN_NB 98   // ceil(100000/1024)

// ---------------- scratch (device globals; no allocation allowed) ----------------
__device__ __half g_out16[(size_t)N_NODES * EMB];        // root accumulator fp16
__device__ __half g_tmp[(size_t)4 * N_NODES * EMB];      // 4 conv output slots (one array)
__device__ __half g_h16[(size_t)N_NODES * EMB];          // h fp16 (GEMM A / pool input)
// 21 weight matrices, transposed [N=128][K=128] fp16:
// slot 0 = emb (K rows 64..127 zero), 1..4 = root, 5..20 = conv (l*4+r)
__device__ __half g_w16[(size_t)21 * 128 * 128];
__device__ int   g_csr_src[(size_t)N_REL * N_EDGES];
__device__ int   g_deg[(size_t)N_REL * N_NODES];
__device__ int   g_off[(size_t)N_REL * (N_NODES + 1)];
__device__ int   g_cur[(size_t)N_REL * N_NODES];
__device__ int   g_bsum[(size_t)N_REL * 128];

// ---------------- helpers ----------------
__device__ __forceinline__ uint32_t smem_u32(const void* p) {
    uint32_t a;
    asm("{ .reg .u64 t; cvta.to.shared.u64 t, %1; cvt.u32.u64 %0, t; }" : "=r"(a) : "l"(p));
    return a;
}
__device__ __forceinline__ void ldsm4(uint32_t& r0, uint32_t& r1, uint32_t& r2, uint32_t& r3,
                                      uint32_t addr) {
    asm volatile("ldmatrix.sync.aligned.m8n8.x4.shared.b16 {%0,%1,%2,%3}, [%4];"
                 : "=r"(r0), "=r"(r1), "=r"(r2), "=r"(r3) : "r"(addr));
}
__device__ __forceinline__ void mma16816(float* d, const uint32_t* a, const uint32_t* b) {
    asm volatile(
        "mma.sync.aligned.m16n8k16.row.col.f32.f16.f16.f32 "
        "{%0,%1,%2,%3}, {%4,%5,%6,%7}, {%8,%9}, {%0,%1,%2,%3};"
        : "+f"(d[0]), "+f"(d[1]), "+f"(d[2]), "+f"(d[3])
        : "r"(a[0]), "r"(a[1]), "r"(a[2]), "r"(a[3]), "r"(b[0]), "r"(b[1]));
}
#define CP_ASYNC16(dst, src, n) \
    asm volatile("cp.async.ca.shared.global [%0], [%1], 16, %2;" \
                 :: "r"(dst), "l"(src), "r"(n))

// ---------------- utility kernels ----------------
__global__ void zero_int_kernel(int* p, int n) {
    int i = blockIdx.x * blockDim.x + threadIdx.x;
    if (i < n) p[i] = 0;
}
__global__ void zero_float_kernel(float* p, int n) {
    int i = blockIdx.x * blockDim.x + threadIdx.x;
    if (i < n) p[i] = 0.0f;
}

__global__ void hist_all_kernel(const int* __restrict__ e0, const int* __restrict__ e1,
                                const int* __restrict__ e2, const int* __restrict__ e3,
                                int* __restrict__ deg) {
    int r = blockIdx.y;
    const int* dst = ((r == 0) ? e0 : (r == 1) ? e1 : (r == 2) ? e2 : e3) + N_EDGES;
    int i = blockIdx.x * 256 + threadIdx.x;
    if (i < N_EDGES) atomicAdd(&deg[(size_t)r * N_NODES + dst[i]], 1);
}

// -------- 3-phase parallel exclusive scan of deg -> off (all relations) --------
__global__ void scan_p1(const int* __restrict__ deg, int* __restrict__ bsum) {
    int r = blockIdx.y, b = blockIdx.x, t = threadIdx.x;
    const int* d = deg + (size_t)r * N_NODES;
    int base = b * 1024 + t * 4;
    int s = 0;
#pragma unroll
    for (int j = 0; j < 4; j++) {
        int idx = base + j;
        if (idx < N_NODES) s += d[idx];
    }
    __shared__ int sm[256];
    sm[t] = s;
    __syncthreads();
    for (int o = 128; o > 0; o >>= 1) {
        if (t < o) sm[t] += sm[t + o];
        __syncthreads();
    }
    if (t == 0) bsum[r * 128 + b] = sm[0];
}
__global__ void scan_p2(int* __restrict__ bsum) {
    __shared__ int sm[512];
    int t = threadIdx.x;
    int r = t >> 7;
    int i = t & 127;
    int v = (i < SCAN_NB) ? bsum[r * 128 + i] : 0;
    sm[t] = v;
    __syncthreads();
    for (int d = 1; d < 128; d <<= 1) {
        int add = (i >= d) ? sm[t - d] : 0;
        __syncthreads();
        sm[t] += add;
        __syncthreads();
    }
    int excl = (i == 0) ? 0 : sm[t - 1];
    if (i < SCAN_NB) bsum[r * 128 + i] = excl;
}
__global__ void scan_p3(const int* __restrict__ deg, const int* __restrict__ bsum,
                        int* __restrict__ off, int* __restrict__ cur) {
    int r = blockIdx.y, b = blockIdx.x, t = threadIdx.x;
    const int* d = deg + (size_t)r * N_NODES;
    int* o = off + (size_t)r * (N_NODES + 1);
    int* c = cur + (size_t)r * N_NODES;
    int base = b * 1024 + t * 4;
    int v[4], pre[4];
    int s = 0;
#pragma unroll
    for (int j = 0; j < 4; j++) {
        int idx = base + j;
        v[j] = (idx < N_NODES) ? d[idx] : 0;
        pre[j] = s;
        s += v[j];
    }
    __shared__ int sm[256];
    sm[t] = s;
    __syncthreads();
    for (int dd = 1; dd < 256; dd <<= 1) {
        int add = (t >= dd) ? sm[t - dd] : 0;
        __syncthreads();
        sm[t] += add;
        __syncthreads();
    }
    int texcl = (t == 0) ? 0 : sm[t - 1];
    int boff = bsum[r * 128 + b];
#pragma unroll
    for (int j = 0; j < 4; j++) {
        int idx = base + j;
        if (idx < N_NODES) {
            int val = boff + texcl + pre[j];
            o[idx] = val;
            c[idx] = val;
        }
    }
    if (b == SCAN_NB - 1 && t == 255) o[N_NODES] = boff + sm[255];
}

__global__ void fill_all_kernel(const int* __restrict__ e0, const int* __restrict__ e1,
                                const int* __restrict__ e2, const int* __restrict__ e3,
                                int* __restrict__ cur, int* __restrict__ csr) {
    int r = blockIdx.y;
    const int* eptr = (r == 0) ? e0 : (r == 1) ? e1 : (r == 2) ? e2 : e3;
    int i = blockIdx.x * 256 + threadIdx.x;
    if (i < N_EDGES) {
        int dnode = eptr[N_EDGES + i];
        int pos = atomicAdd(&cur[(size_t)r * N_NODES + dnode], 1);
        csr[(size_t)r * N_EDGES + pos] = eptr[i];
    }
}

// ---------------- weight conversion ----------------
__global__ void conv_w_kernel(const float* __restrict__ emb_w,
                              const float* __restrict__ root_w,
                              const float* __restrict__ conv_w,
                              __half* __restrict__ w16) {
    int idx = blockIdx.x * blockDim.x + threadIdx.x;
    if (idx >= 21 * 128 * 128) return;
    int s = idx >> 14;
    int rem = idx & 16383;
    int n = rem >> 7;
    int k = rem & 127;
    float v;
    if (s == 0)      v = (k < IN_FEAT) ? emb_w[(size_t)k * EMB + n] : 0.0f;
    else if (s <= 4) v = root_w[((size_t)(s - 1) * EMB + k) * EMB + n];
    else             v = conv_w[((size_t)(s - 5) * EMB + k) * EMB + n];
    w16[idx] = __float2half(v);
}

// ---------------- shared GEMM constants ----------------
#define BK 32
#define SSTR 40
#define BSTR 136
#define ASTR_E 72                            // embed A smem row stride (halves)
#define A_TILE_B (128 * SSTR * 2)            // 10240
#define B_TILE_B (128 * BSTR * 2)            // 34816
#define GEMM_SMEM (B_TILE_B + 2 * A_TILE_B)  // 55296 (layer kernel)
#define EMBED_SMEM (B_TILE_B + 128 * ASTR_E * 2)  // 34816 + 18432 = 53248

// ---------------- fp16 layer GEMM: 2-stage cp.async A, B preload ----------------
// rootFlag==1: y0 -> root slot (slotArg>>16) -> dst0 fp16 + bias; y>=1 conv
//   slot (slotArg&0xFFFF)+y -> tmp + (y-1)*MN.
// rootFlag==0: y -> conv slot (slotArg&0xFFFF)+y -> tmp + y*MN.
__global__ __launch_bounds__(256, 2) void gemm_layer16(
    const __half* __restrict__ A, int M,
    const __half* __restrict__ w_base, int slotArg, int rootFlag,
    const float* __restrict__ bias0,
    __half* __restrict__ dst0, __half* __restrict__ tmp)
{
    const int K = EMB;
    extern __shared__ __half sm_dyn[];
    uint32_t bs_u = smem_u32(sm_dyn);
    uint32_t as_u = bs_u + B_TILE_B;

    int y = blockIdx.y;
    int slot = (rootFlag && y == 0) ? (slotArg >> 16) : ((slotArg & 0xFFFF) + y);
    const __half* W = w_base + (size_t)slot * 16384;

    int tid = threadIdx.x;
    int wid = tid >> 5;
    int lane = tid & 31;
    int wm = wid & 1;
    int wn = wid >> 1;
    int r0 = blockIdx.x * 128;

    // ---- preload B (full 128x128) into smem ----
    for (int idx = tid; idx < 2048; idx += 256) {
        int row = idx >> 4;
        int ch = idx & 15;
        uint32_t soff = (uint32_t)(row * BSTR + ch * 8) * 2u;
        CP_ASYNC16(bs_u + soff,
                   (uint64_t)__cvta_generic_to_global(W + (size_t)row * 128 + ch * 8), 16);
    }
    asm volatile("cp.async.commit_group;");

    float acc[4][4][4];
#pragma unroll
    for (int i = 0; i < 4; i++)
#pragma unroll
        for (int j = 0; j < 4; j++)
#pragma unroll
            for (int q = 0; q < 4; q++) acc[i][j][q] = 0.0f;

    int l_within = lane & 7;
    int l_sel = lane >> 3;
    const int nch = K >> 5;   // 4

    int li0 = tid * 2, li1 = tid * 2 + 1;
    int lr0 = li0 >> 2, lc0 = li0 & 3;
    int lr1 = li1 >> 2, lc1 = li1 & 3;

    auto load_stage = [&](int kc, int st) {
        int k0 = kc * BK;
#pragma unroll
        for (int i = 0; i < 2; i++) {
            int row = i ? lr1 : lr0;
            int ch  = i ? lc1 : lc0;
            int gr = r0 + row;
            int ok = (gr < M) ? 16 : 0;
            int grc = (gr < M) ? gr : 0;
            uint32_t soff = (uint32_t)(row * SSTR + ch * 8) * 2u;
            CP_ASYNC16(as_u + (uint32_t)st * A_TILE_B + soff,
                       (uint64_t)__cvta_generic_to_global(A + (size_t)grc * K + k0 + ch * 8), ok);
        }
        asm volatile("cp.async.commit_group;");
    };

    load_stage(0, 0);
    for (int kc = 0; kc < nch; kc++) {
        int st = kc & 1;
        if (kc + 1 < nch) {
            load_stage(kc + 1, st ^ 1);
            asm volatile("cp.async.wait_group 1;");
        } else {
            asm volatile("cp.async.wait_group 0;");
        }
        __syncthreads();

        uint32_t a_stage = as_u + (uint32_t)st * A_TILE_B;
#pragma unroll
        for (int ks = 0; ks < 2; ks++) {
            uint32_t af[4][4];
            uint32_t bf[4][2];
#pragma unroll
            for (int fm = 0; fm < 4; fm++) {
                int arow = wm * 64 + fm * 16 + (l_sel & 1) * 8 + l_within;
                int acol = ks * 16 + (l_sel >> 1) * 8;
                ldsm4(af[fm][0], af[fm][1], af[fm][2], af[fm][3],
                      a_stage + (uint32_t)(arow * SSTR + acol) * 2u);
            }
#pragma unroll
            for (int g = 0; g < 2; g++) {
                int brow = wn * 32 + g * 16 + (l_sel >> 1) * 8 + l_within;
                int bcol = kc * 32 + ks * 16 + (l_sel & 1) * 8;
                uint32_t r0v, r1v, r2v, r3v;
                ldsm4(r0v, r1v, r2v, r3v,
                      bs_u + (uint32_t)(brow * BSTR + bcol) * 2u);
                bf[2 * g + 0][0] = r0v; bf[2 * g + 0][1] = r1v;
                bf[2 * g + 1][0] = r2v; bf[2 * g + 1][1] = r3v;
            }
#pragma unroll
            for (int fm = 0; fm < 4; fm++)
#pragma unroll
                for (int fn = 0; fn < 4; fn++)
                    mma16816(acc[fm][fn], af[fm], bf[fn]);
        }
        __syncthreads();
    }

    // ---- epilogue (fp16 outputs) ----
    int qrow = lane >> 2;
    int qcol = (lane & 3) * 2;
    bool is_root = (rootFlag && y == 0);
    int cidx = rootFlag ? (y - 1) : y;
    __half* dst = is_root ? dst0 : (tmp + (size_t)cidx * (size_t)N_NODES * EMB);
#pragma unroll
    for (int fm = 0; fm < 4; fm++) {
#pragma unroll
        for (int half_i = 0; half_i < 2; half_i++) {
            int grow = r0 + wm * 64 + fm * 16 + qrow + half_i * 8;
            if (grow >= M) continue;
#pragma unroll
            for (int fn = 0; fn < 4; fn++) {
                int col = wn * 32 + fn * 8 + qcol;
                float v0 = acc[fm][fn][half_i * 2 + 0];
                float v1 = acc[fm][fn][half_i * 2 + 1];
                if (is_root) {
                    v0 += __ldg(&bias0[col]);
                    v1 += __ldg(&bias0[col + 1]);
                }
                *(__half2*)(dst + (size_t)grow * EMB + col) = __floats2half2_rn(v0, v1);
            }
        }
    }
}

// ---------------- embed GEMM: fp32 A loaded + converted in-kernel (K=64) ----------------
__global__ __launch_bounds__(256, 2) void gemm_embed(
    const float* __restrict__ x, int M,
    const __half* __restrict__ w_base,
    const float* __restrict__ bias,
    __half* __restrict__ h16)
{
    const int K = IN_FEAT;   // 64
    extern __shared__ __half sm_dyn[];
    uint32_t bs_u = smem_u32(sm_dyn);
    __half* As = sm_dyn + B_TILE_B / 2;      // B_TILE_B bytes offset (halves ptr)

    const __half* W = w_base;                // slot 0

    int tid = threadIdx.x;
    int wid = tid >> 5;
    int lane = tid & 31;
    int wm = wid & 1;
    int wn = wid >> 1;
    int r0 = blockIdx.x * 128;

    // ---- preload B ----
    for (int idx = tid; idx < 2048; idx += 256) {
        int row = idx >> 4;
        int ch = idx & 15;
        uint32_t soff = (uint32_t)(row * BSTR + ch * 8) * 2u;
        CP_ASYNC16(bs_u + soff,
                   (uint64_t)__cvta_generic_to_global(W + (size_t)row * 128 + ch * 8), 16);
    }
    asm volatile("cp.async.commit_group;");

    // ---- load A (fp32 -> fp16 convert) full tile: 128 rows x 64 cols ----
    for (int c = 0; c < 4; c++) {
        int idx = tid + c * 256;
        int row = idx >> 3;
        int ch = idx & 7;
        int gr = r0 + row;
        __half2 h2[4];
        if (gr < M) {
            const float4* px = (const float4*)(x + (size_t)gr * K + ch * 8);
            float4 f0 = px[0];
            float4 f1 = px[1];
            h2[0] = __floats2half2_rn(f0.x, f0.y);
            h2[1] = __floats2half2_rn(f0.z, f0.w);
            h2[2] = __floats2half2_rn(f1.x, f1.y);
            h2[3] = __floats2half2_rn(f1.z, f1.w);
        } else {
            h2[0] = h2[1] = h2[2] = h2[3] = __floats2half2_rn(0.f, 0.f);
        }
        *(uint4*)(As + row * ASTR_E + ch * 8) = *(uint4*)h2;
    }
    asm volatile("cp.async.wait_group 0;");
    __syncthreads();

    float acc[4][4][4];
#pragma unroll
    for (int i = 0; i < 4; i++)
#pragma unroll
        for (int j = 0; j < 4; j++)
#pragma unroll
            for (int q = 0; q < 4; q++) acc[i][j][q] = 0.0f;

    int l_within = lane & 7;
    int l_sel = lane >> 3;
    uint32_t as_base = smem_u32(As);

    for (int kc = 0; kc < 2; kc++) {
#pragma unroll
        for (int ks = 0; ks < 2; ks++) {
            uint32_t af[4][4];
            uint32_t bf[4][2];
#pragma unroll
            for (int fm = 0; fm < 4; fm++) {
                int arow = wm * 64 + fm * 16 + (l_sel & 1) * 8 + l_within;
                int acol = kc * 32 + ks * 16 + (l_sel >> 1) * 8;
                ldsm4(af[fm][0], af[fm][1], af[fm][2], af[fm][3],
                      as_base + (uint32_t)(arow * ASTR_E + acol) * 2u);
            }
#pragma unroll
            for (int g = 0; g < 2; g++) {
                int brow = wn * 32 + g * 16 + (l_sel >> 1) * 8 + l_within;
                int bcol = kc * 32 + ks * 16 + (l_sel & 1) * 8;
                uint32_t r0v, r1v, r2v, r3v;
                ldsm4(r0v, r1v, r2v, r3v,
                      bs_u + (uint32_t)(brow * BSTR + bcol) * 2u);
                bf[2 * g + 0][0] = r0v; bf[2 * g + 0][1] = r1v;
                bf[2 * g + 1][0] = r2v; bf[2 * g + 1][1] = r3v;
            }
#pragma unroll
            for (int fm = 0; fm < 4; fm++)
#pragma unroll
                for (int fn = 0; fn < 4; fn++)
                    mma16816(acc[fm][fn], af[fm], bf[fn]);
        }
    }

    int qrow = lane >> 2;
    int qcol = (lane & 3) * 2;
#pragma unroll
    for (int fm = 0; fm < 4; fm++) {
#pragma unroll
        for (int half_i = 0; half_i < 2; half_i++) {
            int grow = r0 + wm * 64 + fm * 16 + qrow + half_i * 8;
            if (grow >= M) continue;
#pragma unroll
            for (int fn = 0; fn < 4; fn++) {
                int col = wn * 32 + fn * 8 + qcol;
                float v0 = acc[fm][fn][half_i * 2 + 0] + __ldg(&bias[col]);
                float v1 = acc[fm][fn][half_i * 2 + 1] + __ldg(&bias[col + 1]);
                *(__half2*)(h16 + (size_t)grow * EMB + col) = __floats2half2_rn(v0, v1);
            }
        }
    }
}

// ---------------- pair-fused aggregation (warp per node, fp16) ----------------
__device__ __forceinline__ void agg_one_rel16(
    const __half* __restrict__ msg, const int* __restrict__ off,
    const int* __restrict__ csr, int node, int lane, float4& acc)
{
    int s = __ldg(&off[node]);
    int e = __ldg(&off[node + 1]);
    if (s >= e) return;
    float4 m = make_float4(-FLT_MAX, -FLT_MAX, -FLT_MAX, -FLT_MAX);
    int i = s;
    for (; i + 1 < e; i += 2) {
        int s0 = __ldg(&csr[i]);
        int s1 = __ldg(&csr[i + 1]);
        uint2 u0 = *(const uint2*)(msg + (size_t)s0 * EMB + lane * 4);
        uint2 u1 = *(const uint2*)(msg + (size_t)s1 * EMB + lane * 4);
        float2 a0 = __half22float2(*(__half2*)&u0.x);
        float2 b0 = __half22float2(*(__half2*)&u0.y);
        float2 a1 = __half22float2(*(__half2*)&u1.x);
        float2 b1 = __half22float2(*(__half2*)&u1.y);
        m.x = fmaxf(m.x, fmaxf(a0.x, a1.x));
        m.y = fmaxf(m.y, fmaxf(a0.y, a1.y));
        m.z = fmaxf(m.z, fmaxf(b0.x, b1.x));
        m.w = fmaxf(m.w, fmaxf(b0.y, b1.y));
    }
    if (i < e) {
        int s0 = __ldg(&csr[i]);
        uint2 u0 = *(const uint2*)(msg + (size_t)s0 * EMB + lane * 4);
        float2 a0 = __half22float2(*(__half2*)&u0.x);
        float2 b0 = __half22float2(*(__half2*)&u0.y);
        m.x = fmaxf(m.x, a0.x);
        m.y = fmaxf(m.y, a0.y);
        m.z = fmaxf(m.z, b0.x);
        m.w = fmaxf(m.w, b0.y);
    }
    acc.x += m.x; acc.y += m.y; acc.z += m.z; acc.w += m.w;
}

__global__ __launch_bounds__(256) void agg_pair_kernel(
    const __half* __restrict__ msg0, const __half* __restrict__ msg1,
    const int* __restrict__ off0, const int* __restrict__ csr0,
    const int* __restrict__ off1, const int* __restrict__ csr1,
    __half* __restrict__ out16, __half* __restrict__ h16,
    int last)
{
    int node = blockIdx.x * 8 + (threadIdx.x >> 5);
    if (node >= N_NODES) return;
    int lane = threadIdx.x & 31;
    size_t base = (size_t)node * EMB + lane * 4;

    uint2 ru = __ldcs((const uint2*)(out16 + base));
    float2 ra = __half22float2(*(__half2*)&ru.x);
    float2 rb = __half22float2(*(__half2*)&ru.y);
    float4 acc = make_float4(ra.x, ra.y, rb.x, rb.y);

    agg_one_rel16(msg0, off0, csr0, node, lane, acc);
    agg_one_rel16(msg1, off1, csr1, node, lane, acc);

    if (!last) {
        __half2 p0 = __floats2half2_rn(acc.x, acc.y);
        __half2 p1 = __floats2half2_rn(acc.z, acc.w);
        uint2 uo; uo.x = *(uint32_t*)&p0; uo.y = *(uint32_t*)&p1;
        __stcs((uint2*)(out16 + base), uo);
        return;
    }

    acc.x = fmaxf(acc.x, 0.0f);
    acc.y = fmaxf(acc.y, 0.0f);
    acc.z = fmaxf(acc.z, 0.0f);
    acc.w = fmaxf(acc.w, 0.0f);
    *(__half2*)(h16 + base) = __floats2half2_rn(acc.x, acc.y);
    *(__half2*)(h16 + base + 2) = __floats2half2_rn(acc.z, acc.w);
}

// ---------------- global add pool (reads fp16 h, fp32 accumulate) ----------------
__global__ __launch_bounds__(128) void pool_kernel(
    const __half* __restrict__ h16, const int* __restrict__ batch,
    float* __restrict__ out, int n)
{
    const int NPB = 256;
    int f = threadIdx.x;
    int n0 = blockIdx.x * NPB;
    if (n0 >= n) return;
    int nend = min(n0 + NPB, n);
    float acc = 0.0f;
    int cur = batch[n0];
    for (int i = n0; i < nend; i++) {
        int b = batch[i];
        if (b != cur) {
            atomicAdd(&out[(size_t)cur * EMB + f], acc);
            acc = 0.0f;
            cur = b;
        }
        acc += __half2float(h16[(size_t)i * EMB + f]);
    }
    atomicAdd(&out[(size_t)cur * EMB + f], acc);
}

// ---------------- host launch ----------------
extern "C" void kernel_launch(void* const* d_in, const int* in_sizes, int n_in,
                              void* d_out, int out_size)
{
    const float* x      = (const float*)d_in[0];
    const int*   e0     = (const int*)d_in[1];
    const int*   e1     = (const int*)d_in[2];
    const int*   e2     = (const int*)d_in[3];
    const int*   e3     = (const int*)d_in[4];
    const int*   batch  = (const int*)d_in[5];
    const float* emb_w  = (const float*)d_in[6];
    const float* emb_b  = (const float*)d_in[7];
    const float* root_w = (const float*)d_in[8];
    const float* root_b = (const float*)d_in[9];
    const float* conv_w = (const float*)d_in[10];
    float* out = (float*)d_out;

    void *p_out16, *p_tmp, *p_h16, *p_w16;
    void *p_csr, *p_deg, *p_off, *p_cur, *p_bsum;
    cudaGetSymbolAddress(&p_out16, g_out16);
    cudaGetSymbolAddress(&p_tmp, g_tmp);
    cudaGetSymbolAddress(&p_h16, g_h16);
    cudaGetSymbolAddress(&p_w16, g_w16);
    cudaGetSymbolAddress(&p_csr, g_csr_src);
    cudaGetSymbolAddress(&p_deg, g_deg);
    cudaGetSymbolAddress(&p_off, g_off);
    cudaGetSymbolAddress(&p_cur, g_cur);
    cudaGetSymbolAddress(&p_bsum, g_bsum);
    __half* out16 = (__half*)p_out16;
    __half* tmp  = (__half*)p_tmp;
    __half* h16  = (__half*)p_h16;
    __half* w16  = (__half*)p_w16;
    int* csr = (int*)p_csr;
    int* deg = (int*)p_deg;
    int* off = (int*)p_off;
    int* cur = (int*)p_cur;
    int* bsum = (int*)p_bsum;

    const size_t MN = (size_t)N_NODES * EMB;

    static bool attr_set = []() {
        cudaFuncSetAttribute(gemm_layer16, cudaFuncAttributeMaxDynamicSharedMemorySize, GEMM_SMEM);
        cudaFuncSetAttribute(gemm_embed, cudaFuncAttributeMaxDynamicSharedMemorySize, EMBED_SMEM);
        return true;
    }();
    (void)attr_set;

    static cudaStream_t s2 = []() {
        cudaStream_t s;
        cudaStreamCreateWithFlags(&s, cudaStreamNonBlocking);
        return s;
    }();
    static cudaEvent_t evFork = []() {
        cudaEvent_t e; cudaEventCreateWithFlags(&e, cudaEventDisableTiming); return e;
    }();
    static cudaEvent_t evG1 = []() {
        cudaEvent_t e; cudaEventCreateWithFlags(&e, cudaEventDisableTiming); return e;
    }();
    static cudaEvent_t evG2 = []() {
        cudaEvent_t e; cudaEventCreateWithFlags(&e, cudaEventDisableTiming); return e;
    }();
    static cudaEvent_t evA = []() {
        cudaEvent_t e; cudaEventCreateWithFlags(&e, cudaEventDisableTiming); return e;
    }();

    const int EB = (N_EDGES + 255) / 256;
    const int GB = (N_NODES + 127) / 128;
    const int AB = (N_NODES + 7) / 8;

    // ---- fork CSR build to s2 (overlaps with weight conversion + embed GEMM) ----
    cudaEventRecord(evFork, 0);
    cudaStreamWaitEvent(s2, evFork, 0);
    zero_int_kernel<<<(N_REL * N_NODES + 255) / 256, 256, 0, s2>>>(deg, N_REL * N_NODES);
    hist_all_kernel<<<dim3(EB, N_REL), 256, 0, s2>>>(e0, e1, e2, e3, deg);
    scan_p1<<<dim3(SCAN_NB, N_REL), 256, 0, s2>>>(deg, bsum);
    scan_p2<<<1, 512, 0, s2>>>(bsum);
    scan_p3<<<dim3(SCAN_NB, N_REL), 256, 0, s2>>>(deg, bsum, off, cur);
    fill_all_kernel<<<dim3(EB, N_REL), 256, 0, s2>>>(e0, e1, e2, e3, cur, csr);
    // CSR work stays on s2; aggregations are enqueued on s2 after it, so ordering
    // with the CSR build is implicit (same stream).

    // ---- main stream: weight convert + embed (fp32 x consumed directly) ----
    conv_w_kernel<<<(21 * 128 * 128 + 255) / 256, 256>>>(emb_w, root_w, conv_w, w16);
    gemm_embed<<<GB, 256, EMBED_SMEM>>>(x, N_NODES, w16, emb_b, h16);

    for (int l = 0; l < N_LAYERS; l++) {
        // gemm1: root + conv0 + conv1 -> out16, tmp[0], tmp[MN]   (stream 0)
        int slotArg1 = ((1 + l) << 16) | (4 + 4 * l);   // y1->5+4l, y2->6+4l
        gemm_layer16<<<dim3(GB, 3), 256, GEMM_SMEM>>>(h16, N_NODES, w16,
                                                      slotArg1, /*rootFlag=*/1,
                                                      root_b + (size_t)l * EMB,
                                                      out16, tmp);
        cudaEventRecord(evG1, 0);
        // agg01 on s2, overlapped with gemm2 below
        cudaStreamWaitEvent(s2, evG1, 0);
        agg_pair_kernel<<<AB, 256, 0, s2>>>(tmp, tmp + MN,
                                            off, csr,
                                            off + (size_t)(N_NODES + 1), csr + (size_t)N_EDGES,
                                            out16, h16, 0);
        // gemm2: conv2 + conv3 -> tmp[2MN], tmp[3MN]   (stream 0, disjoint slots)
        int slotArg2 = 7 + 4 * l;                        // y0->7+4l, y1->8+4l
        gemm_layer16<<<dim3(GB, 2), 256, GEMM_SMEM>>>(h16, N_NODES, w16,
                                                      slotArg2, /*rootFlag=*/0,
                                                      (const float*)0,
                                                      (__half*)0, tmp + 2 * MN);
        cudaEventRecord(evG2, 0);
        // agg23 on s2 (after agg01, same stream; waits gemm2)
        cudaStreamWaitEvent(s2, evG2, 0);
        agg_pair_kernel<<<AB, 256, 0, s2>>>(tmp + 2 * MN, tmp + 3 * MN,
                                            off + (size_t)2 * (N_NODES + 1), csr + (size_t)2 * N_EDGES,
                                            off + (size_t)3 * (N_NODES + 1), csr + (size_t)3 * N_EDGES,
                                            out16, h16, 1);
        cudaEventRecord(evA, s2);
        cudaStreamWaitEvent(0, evA, 0);    // h16 ready before next layer's gemm1
    }

    // ---- global add pool (stream 0, after final join) ----
    zero_float_kernel<<<(N_GRAPHS * EMB + 255) / 256, 256>>>(out, N_GRAPHS * EMB);
    pool_kernel<<<(N_NODES + 255) / 256, 128>>>(h16, batch, out, N_NODES);
}